// round 13
// baseline (speedup 1.0000x reference)
#include <cuda_runtime.h>
#include <cuda_bf16.h>
#include <math_constants.h>
#include <cstdint>

#define B_N 32768
#define D_N 128
#define K_N 4096
#define CAP 128
#define DELTA_C 2.5e-4f
#define NTILES 32

// phase-1 smem layout (bytes). Rows padded to 272B (136 bf16) for conflict-free LDSM.
#define ROWB 272
#define XS_OFF   0
#define E0_OFF   34816
#define E1_OFF   69632
#define SCNT_OFF 104448
#define SM_TOTAL 104960

// tail (rescore) smem layout — reuses [0, SCNT_OFF) after the MMA loop
#define TXS_OFF   0                       // fp32 x chunk [16][132]
#define TSL_OFF   8448                    // slist [16][CAP]
#define TSC_OFF   (TSL_OFF + 16*CAP*4)    // scnt2 [16]
#define TSW_OFF   (TSC_OFF + 64)          // swe[8], swq[8]

__device__ __nv_bfloat16 g_eb[K_N * D_N];
__device__ int2   g_cand[(size_t)B_N * CAP];   // .x = bf16-GEMM score bits, .y = index
__device__ float  g_esq[K_N];
__device__ int    g_counts[K_N];
__device__ double g_sum_e, g_sum_q;

__device__ __forceinline__ uint32_t smem_u32(const void* p) {
    uint32_t a;
    asm("{ .reg .u64 t; cvta.to.shared.u64 t, %1; cvt.u32.u64 %0, t; }"
        : "=r"(a) : "l"(p));
    return a;
}
__device__ __forceinline__ void ldsm_x4(uint32_t& r0, uint32_t& r1,
                                        uint32_t& r2, uint32_t& r3, uint32_t addr) {
    asm volatile("ldmatrix.sync.aligned.m8n8.x4.shared.b16 {%0,%1,%2,%3}, [%4];"
        : "=r"(r0), "=r"(r1), "=r"(r2), "=r"(r3) : "r"(addr));
}
__device__ __forceinline__ void mma16816(float* c, uint32_t a0, uint32_t a1,
                                         uint32_t a2, uint32_t a3,
                                         uint32_t b0, uint32_t b1) {
    asm volatile("mma.sync.aligned.m16n8k16.row.col.f32.bf16.bf16.f32 "
        "{%0,%1,%2,%3}, {%4,%5,%6,%7}, {%8,%9}, {%0,%1,%2,%3};"
        : "+f"(c[0]), "+f"(c[1]), "+f"(c[2]), "+f"(c[3])
        : "r"(a0), "r"(a1), "r"(a2), "r"(a3), "r"(b0), "r"(b1));
}
__device__ __forceinline__ uint32_t packbf(float a, float b) {
    return ((uint32_t)__bfloat16_as_ushort(__float2bfloat16_rn(b)) << 16) |
            (uint32_t)__bfloat16_as_ushort(__float2bfloat16_rn(a));
}
#define CP_ASYNC16(dst, src) \
    asm volatile("cp.async.cg.shared.global [%0], [%1], 16;" \
        :: "r"(dst), "l"(src) : "memory")
#define CP_COMMIT() asm volatile("cp.async.commit_group;" ::: "memory")
#define CP_WAIT(n)  asm volatile("cp.async.wait_group %0;" :: "n"(n) : "memory")

// ---------------------------------------------------------------------------
// init: warp per E row — |e|^2 (fp64, shuffle-reduced), bf16 convert, zeroing
// ---------------------------------------------------------------------------
__global__ void __launch_bounds__(256) k_init(const float* __restrict__ E) {
    const int warp = threadIdx.x >> 5;
    const int lane = threadIdx.x & 31;
    const int row  = blockIdx.x * 8 + warp;

    float4 v = ((const float4*)(E + (size_t)row * D_N))[lane];
    double s = 0.0;
    s += (double)v.x * (double)v.x;
    s += (double)v.y * (double)v.y;
    s += (double)v.z * (double)v.z;
    s += (double)v.w * (double)v.w;
    #pragma unroll
    for (int off = 16; off > 0; off >>= 1)
        s += __shfl_xor_sync(0xffffffffu, s, off);

    uint2 o;
    o.x = packbf(v.x, v.y);
    o.y = packbf(v.z, v.w);
    ((uint2*)g_eb)[(size_t)row * 32 + lane] = o;

    if (lane == 0) { g_esq[row] = (float)s; g_counts[row] = 0; }
    if (row == 0 && lane == 0) { g_sum_e = 0.0; g_sum_q = 0.0; }
}

// ---------------------------------------------------------------------------
// phase1 (fused): bf16 mma.sync GEMM with per-half register-threshold
// candidate selection (R8-identical main loop), then an in-CTA rescore +
// gather tail over this CTA's own 128 rows (R12-identical per-row logic).
// ---------------------------------------------------------------------------
__global__ void __launch_bounds__(256, 2) k_phase1(
    const float* __restrict__ X, const float* __restrict__ E,
    float* __restrict__ out, int out_size)
{
    extern __shared__ char smem[];
    int* scnt = (int*)(smem + SCNT_OFF);   // [128]

    const int tid  = threadIdx.x;
    const int lane = tid & 31;
    const int wid  = tid >> 5;
    const int wm   = wid >> 1;          // 0..3  (rows 32*wm .. +32)
    const int wn   = wid & 1;           // 0..1  (cols 64*wn .. +64)
    const int row0 = blockIdx.x * 128;

    if (tid < 128) scnt[tid] = 0;

    const uint32_t sb = smem_u32(smem);

    // issue E tile 0 via cp.async (group 0)
    #pragma unroll
    for (int i = 0; i < 8; i++) {
        int m = tid + i * 256; int r = m >> 4, c16 = m & 15;
        uint32_t dst = sb + E0_OFF + (uint32_t)(r * ROWB + c16 * 16);
        const char* src = (const char*)g_eb + (size_t)r * 256 + c16 * 16;
        CP_ASYNC16(dst, src);
    }
    CP_COMMIT();

    // X tile: load fp32, convert to bf16, store padded (overlaps with cp.async)
    #pragma unroll
    for (int i = 0; i < 8; i++) {
        int m = tid + i * 256; int r = m >> 4, c16 = m & 15;
        float4 f0 = ((const float4*)X)[(size_t)(row0 + r) * 32 + c16 * 2];
        float4 f1 = ((const float4*)X)[(size_t)(row0 + r) * 32 + c16 * 2 + 1];
        uint4 o;
        o.x = packbf(f0.x, f0.y);
        o.y = packbf(f0.z, f0.w);
        o.z = packbf(f1.x, f1.y);
        o.w = packbf(f1.z, f1.w);
        *(uint4*)(smem + XS_OFF + r * ROWB + c16 * 16) = o;
    }
    __syncthreads();

    const uint32_t pA = sb + XS_OFF + (uint32_t)((wm * 32 + (lane & 15)) * ROWB)
                        + (uint32_t)((lane >> 4) * 8 * 2);
    const int n_lane = ((lane >> 4) << 3) + (lane & 7);
    const uint32_t pB_off = (uint32_t)((wn * 64 + n_lane) * ROWB)
                            + (uint32_t)(((lane >> 3) & 1) * 8 * 2);

    const int qr = lane >> 2;           // quad row id 0..7
    const int qc = lane & 3;

    // per-half running row maxima (registers)
    float thrA[2] = { -CUDART_INF_F, -CUDART_INF_F };
    float thrB[2] = { -CUDART_INF_F, -CUDART_INF_F };

    for (int t = 0; t < NTILES; t++) {
        const int buf = t & 1;

        // stage tile t+1 into the other buffer, then wait for tile t
        if (t + 1 < NTILES) {
            const int nb = (t + 1) & 1;
            const uint32_t ebase = sb + (nb ? E1_OFF : E0_OFF);
            #pragma unroll
            for (int i = 0; i < 8; i++) {
                int m = tid + i * 256; int r = m >> 4, c16 = m & 15;
                uint32_t dst = ebase + (uint32_t)(r * ROWB + c16 * 16);
                const char* src = (const char*)g_eb
                                  + (size_t)((t + 1) * 128 + r) * 256 + c16 * 16;
                CP_ASYNC16(dst, src);
            }
            CP_COMMIT();
            CP_WAIT(1);
        } else {
            CP_WAIT(0);
        }
        __syncthreads();

        const uint32_t pB = sb + (buf ? E1_OFF : E0_OFF) + pB_off;

        float acc[2][8][4];
        #pragma unroll
        for (int mt = 0; mt < 2; mt++)
            #pragma unroll
            for (int nt = 0; nt < 8; nt++)
                #pragma unroll
                for (int j = 0; j < 4; j++) acc[mt][nt][j] = 0.0f;

        #pragma unroll
        for (int s = 0; s < 8; s++) {
            uint32_t a[2][4];
            #pragma unroll
            for (int mt = 0; mt < 2; mt++)
                ldsm_x4(a[mt][0], a[mt][1], a[mt][2], a[mt][3],
                        pA + (uint32_t)(mt * 16 * ROWB) + (uint32_t)(s * 32));
            uint32_t b[4][4];
            #pragma unroll
            for (int p = 0; p < 4; p++)
                ldsm_x4(b[p][0], b[p][1], b[p][2], b[p][3],
                        pB + (uint32_t)(p * 16 * ROWB) + (uint32_t)(s * 32));
            #pragma unroll
            for (int mt = 0; mt < 2; mt++)
                #pragma unroll
                for (int nt = 0; nt < 8; nt++) {
                    uint32_t b0 = (nt & 1) ? b[nt >> 1][2] : b[nt >> 1][0];
                    uint32_t b1 = (nt & 1) ? b[nt >> 1][3] : b[nt >> 1][1];
                    mma16816(acc[mt][nt], a[mt][0], a[mt][1], a[mt][2], a[mt][3],
                             b0, b1);
                }
        }

        // ---- epilogue: warp-local row maxima, guarded emission ----
        #pragma unroll
        for (int mt = 0; mt < 2; mt++) {
            float ma = -CUDART_INF_F, mb = -CUDART_INF_F;
            #pragma unroll
            for (int nt = 0; nt < 8; nt++) {
                ma = fmaxf(ma, fmaxf(acc[mt][nt][0], acc[mt][nt][1]));
                mb = fmaxf(mb, fmaxf(acc[mt][nt][2], acc[mt][nt][3]));
            }
            ma = fmaxf(ma, __shfl_xor_sync(0xffffffffu, ma, 1));
            ma = fmaxf(ma, __shfl_xor_sync(0xffffffffu, ma, 2));
            mb = fmaxf(mb, __shfl_xor_sync(0xffffffffu, mb, 1));
            mb = fmaxf(mb, __shfl_xor_sync(0xffffffffu, mb, 2));
            const bool anyA = (ma >= thrA[mt] - DELTA_C);
            const bool anyB = (mb >= thrB[mt] - DELTA_C);
            thrA[mt] = fmaxf(thrA[mt], ma);
            thrB[mt] = fmaxf(thrB[mt], mb);
            const int rA = wm * 32 + mt * 16 + qr;
            const int rB = rA + 8;
            if (anyA) {
                const float cutA = thrA[mt] - DELTA_C;
                #pragma unroll
                for (int nt = 0; nt < 8; nt++) {
                    int kb = t * 128 + wn * 64 + nt * 8 + 2 * qc;
                    if (acc[mt][nt][0] >= cutA) {
                        int p = atomicAdd(&scnt[rA], 1);
                        if (p < CAP) g_cand[(size_t)(row0 + rA) * CAP + p] =
                            make_int2(__float_as_int(acc[mt][nt][0]), kb);
                    }
                    if (acc[mt][nt][1] >= cutA) {
                        int p = atomicAdd(&scnt[rA], 1);
                        if (p < CAP) g_cand[(size_t)(row0 + rA) * CAP + p] =
                            make_int2(__float_as_int(acc[mt][nt][1]), kb + 1);
                    }
                }
            }
            if (anyB) {
                const float cutB = thrB[mt] - DELTA_C;
                #pragma unroll
                for (int nt = 0; nt < 8; nt++) {
                    int kb = t * 128 + wn * 64 + nt * 8 + 2 * qc;
                    if (acc[mt][nt][2] >= cutB) {
                        int p = atomicAdd(&scnt[rB], 1);
                        if (p < CAP) g_cand[(size_t)(row0 + rB) * CAP + p] =
                            make_int2(__float_as_int(acc[mt][nt][2]), kb);
                    }
                    if (acc[mt][nt][3] >= cutB) {
                        int p = atomicAdd(&scnt[rB], 1);
                        if (p < CAP) g_cand[(size_t)(row0 + rB) * CAP + p] =
                            make_int2(__float_as_int(acc[mt][nt][3]), kb + 1);
                    }
                }
            }
        }
        __syncthreads();
    }

    // ======================= fused rescore + gather tail =====================
    // Reuses smem [0, SCNT_OFF). scnt (counts) remains valid at SCNT_OFF.
    float*  xsf   = (float*) (smem + TXS_OFF);   // [16][132] fp32 x chunk
    int*    slist = (int*)   (smem + TSL_OFF);   // [16][CAP]
    int*    scnt2 = (int*)   (smem + TSC_OFF);   // [16]
    double* swe   = (double*)(smem + TSW_OFF);   // [8]
    double* swq   = swe + 8;                     // [8]

    const int grp = lane >> 4;      // 0..1: row within warp
    const int l16 = lane & 15;      // lane within 16-lane group
    const int rowL = wid * 2 + grp; // 0..15 within chunk

    double se_tot = 0.0, sq_tot = 0.0;

    for (int c = 0; c < 8; c++) {
        __syncthreads();
        // load fp32 X for rows [row0 + c*16, +16)
        #pragma unroll
        for (int i = 0; i < 2; i++) {
            int m = tid + i * 256;          // 0..511
            int r = m >> 5, cc = m & 31;
            float4 v = ((const float4*)X)[(size_t)(row0 + c * 16 + r) * 32 + cc];
            *(float4*)&xsf[r * 132 + cc * 4] = v;
        }
        if (tid < 16) scnt2[tid] = 0;
        __syncthreads();

        const int lrow = c * 16 + rowL;     // 0..127
        const int row  = row0 + lrow;
        const float* xr = &xsf[rowL * 132];

        // A = |x|^2 in fp64, reduced within the 16-lane group
        double s = 0.0;
        #pragma unroll
        for (int i = 0; i < 8; i++) { double v = (double)xr[l16 * 8 + i]; s += v * v; }
        #pragma unroll
        for (int off = 1; off < 16; off <<= 1)
            s += __shfl_xor_sync(0xffffffffu, s, off);
        float A = (float)s;

        int n = scnt[lrow];
        float best = CUDART_INF_F;
        int bi = 0x7fffffff;

        if (n <= CAP) {
            const int2* cd = &g_cand[(size_t)row * CAP];
            // global bf16-score max over this row's candidates
            float vmax = -CUDART_INF_F;
            for (int j = l16; j < n; j += 16)
                vmax = fmaxf(vmax, __int_as_float(cd[j].x));
            #pragma unroll
            for (int off = 1; off < 16; off <<= 1)
                vmax = fmaxf(vmax, __shfl_xor_sync(0xffffffffu, vmax, off));
            const float cut = vmax - DELTA_C;
            // compact survivors into smem
            for (int j = l16; j < n; j += 16) {
                int2 cc2 = cd[j];
                if (__int_as_float(cc2.x) >= cut) {
                    int p = atomicAdd(&scnt2[rowL], 1);
                    slist[rowL * CAP + p] = cc2.y;
                }
            }
            __syncwarp();
            const int m = scnt2[rowL];
            for (int si = l16; si < m; si += 16) {
                int k = slist[rowL * CAP + si];
                const float4* e4 = (const float4*)(E + (size_t)k * D_N);
                float acc = 0.0f;
                #pragma unroll 8
                for (int i = 0; i < 32; i++) {
                    float4 xv = *(const float4*)&xr[i * 4];
                    float4 ev = e4[i];
                    acc = __fmaf_rn(xv.x, ev.x, acc);
                    acc = __fmaf_rn(xv.y, ev.y, acc);
                    acc = __fmaf_rn(xv.z, ev.z, acc);
                    acc = __fmaf_rn(xv.w, ev.w, acc);
                }
                float tsum = __fadd_rn(A, g_esq[k]);
                float v = __fmaf_rn(-2.0f, acc, tsum);
                if (v < best || (v == best && k < bi)) { best = v; bi = k; }
            }
        } else {
            // safety fallback: exact full scan (unreachable in practice)
            for (int k = l16; k < K_N; k += 16) {
                const float4* e4 = (const float4*)(E + (size_t)k * D_N);
                float acc = 0.0f;
                #pragma unroll 8
                for (int i = 0; i < 32; i++) {
                    float4 xv = *(const float4*)&xr[i * 4];
                    float4 ev = e4[i];
                    acc = __fmaf_rn(xv.x, ev.x, acc);
                    acc = __fmaf_rn(xv.y, ev.y, acc);
                    acc = __fmaf_rn(xv.z, ev.z, acc);
                    acc = __fmaf_rn(xv.w, ev.w, acc);
                }
                float tsum = __fadd_rn(A, g_esq[k]);
                float v = __fmaf_rn(-2.0f, acc, tsum);
                if (v < best || (v == best && k < bi)) { best = v; bi = k; }
            }
        }
        // butterfly reduce within 16-lane group -> all lanes hold (best, bi)
        #pragma unroll
        for (int off = 1; off < 16; off <<= 1) {
            float ov = __shfl_xor_sync(0xffffffffu, best, off);
            int   oi = __shfl_xor_sync(0xffffffffu, bi, off);
            if (ov < best || (ov == best && oi < bi)) { best = ov; bi = oi; }
        }

        // ---- gather: straight-through output + loss sums + histogram ----
        const float4* e4 = (const float4*)(E + (size_t)bi * D_N);
        float4 q0 = e4[l16 * 2], q1 = e4[l16 * 2 + 1];
        float4 x0 = *(const float4*)&xr[l16 * 8];
        float4 x1 = *(const float4*)&xr[l16 * 8 + 4];
        float4 o0, o1;
#define VQ_STEP(o, q, x) { \
        float de = __fsub_rn(q, x); float qs = __fadd_rn(x, de); \
        float dq = __fsub_rn(qs, x); \
        o = qs; se_tot += (double)de * (double)de; sq_tot += (double)dq * (double)dq; }
        VQ_STEP(o0.x, q0.x, x0.x)  VQ_STEP(o0.y, q0.y, x0.y)
        VQ_STEP(o0.z, q0.z, x0.z)  VQ_STEP(o0.w, q0.w, x0.w)
        VQ_STEP(o1.x, q1.x, x1.x)  VQ_STEP(o1.y, q1.y, x1.y)
        VQ_STEP(o1.z, q1.z, x1.z)  VQ_STEP(o1.w, q1.w, x1.w)
#undef VQ_STEP
        ((float4*)out)[(size_t)row * 32 + l16 * 2]     = o0;
        ((float4*)out)[(size_t)row * 32 + l16 * 2 + 1] = o1;

        if (l16 == 0) {
            atomicAdd(&g_counts[bi], 1);
            if (out_size >= B_N * D_N + B_N)
                out[(size_t)B_N * D_N + row] = (float)bi;
        }
    }

    // block-reduce loss sums (once per CTA)
    #pragma unroll
    for (int off = 16; off > 0; off >>= 1) {
        se_tot += __shfl_down_sync(0xffffffffu, se_tot, off);
        sq_tot += __shfl_down_sync(0xffffffffu, sq_tot, off);
    }
    if (lane == 0) { swe[wid] = se_tot; swq[wid] = sq_tot; }
    __syncthreads();
    if (tid == 0) {
        double te = 0.0, tq = 0.0;
        #pragma unroll
        for (int i = 0; i < 8; i++) { te += swe[i]; tq += swq[i]; }
        atomicAdd(&g_sum_e, te);
        atomicAdd(&g_sum_q, tq);
    }
}

// ---------------------------------------------------------------------------
// final: entropy + scalar outputs in one kernel (single CTA)
// ---------------------------------------------------------------------------
__global__ void k_final(float* __restrict__ out, int out_size) {
    if (out_size < B_N * D_N + B_N + 4) return;
    __shared__ double sh[512];
    int tid = threadIdx.x;
    double h = 0.0;
    #pragma unroll
    for (int r = 0; r < K_N / 512; r++) {
        int k = r * 512 + tid;
        float p = __fmul_rn((float)g_counts[k], 1.0f / 32768.0f);
        float t = __fmul_rn(p, logf(__fadd_rn(p, 1e-10f)));
        h += (double)t;
    }
    sh[tid] = h;
    __syncthreads();
    for (int s = 256; s > 0; s >>= 1) {
        if (tid < s) sh[tid] += sh[tid + s];
        __syncthreads();
    }
    if (tid == 0) {
        float H = (float)sh[0];
        float perp = expf(-H);
        double n = (double)B_N * (double)D_N;
        float e = (float)(g_sum_e / n);
        float q = (float)(g_sum_q / n);
        float vq = __fadd_rn(q, __fmul_rn(0.25f, e));
        float* s4 = out + (size_t)B_N * D_N + B_N;
        s4[0] = vq; s4[1] = e; s4[2] = q; s4[3] = perp;
    }
}

// ---------------------------------------------------------------------------
extern "C" void kernel_launch(void* const* d_in, const int* in_sizes, int n_in,
                              void* d_out, int out_size)
{
    const float* X = (const float*)d_in[0];
    const float* E = (const float*)d_in[1];
    if (n_in >= 2 && in_sizes[0] == K_N * D_N && in_sizes[1] == B_N * D_N) {
        X = (const float*)d_in[1];
        E = (const float*)d_in[0];
    }
    float* out = (float*)d_out;

    static bool attr_set = false;
    if (!attr_set) {
        cudaFuncSetAttribute(k_phase1,
                             cudaFuncAttributeMaxDynamicSharedMemorySize,
                             SM_TOTAL);
        attr_set = true;
    }

    k_init<<<K_N / 8, 256>>>(E);
    k_phase1<<<B_N / 128, 256, SM_TOTAL>>>(X, E, out, out_size);
    k_final<<<1, 512>>>(out, out_size);
}

// round 14
// speedup vs baseline: 1.0124x; 1.0124x over previous
#include <cuda_runtime.h>
#include <cuda_bf16.h>
#include <math_constants.h>
#include <cstdint>

#define B_N 32768
#define D_N 128
#define K_N 4096
#define CAP 128
#define DELTA_C 2.5e-4f
#define NTILES 32

// phase-1 smem layout (bytes). Rows padded to 272B (136 bf16) for conflict-free LDSM.
#define ROWB 272
#define XS_OFF   0
#define E0_OFF   34816
#define E1_OFF   69632
#define SCNT_OFF 104448
#define RMAX_OFF 104960                   // [128][2] float row maxima
#define SM_TOTAL 105984

// tail (rescore) smem layout — reuses [0, SCNT_OFF) after the MMA loop
#define TXS_OFF   0                       // fp32 x chunk [16][132]
#define TSL_OFF   8448                    // slist [16][CAP]
#define TSC_OFF   (TSL_OFF + 16*CAP*4)    // scnt2 [16]
#define TSW_OFF   (TSC_OFF + 64)          // swe[8], swq[8], flag

__device__ __nv_bfloat16 g_eb[K_N * D_N];
__device__ int2   g_cand[(size_t)B_N * CAP];   // .x = bf16-GEMM score bits, .y = index
__device__ float  g_esq[K_N];
__device__ int    g_counts[K_N];
__device__ double g_sum_e, g_sum_q;
__device__ int    g_done;

__device__ __forceinline__ uint32_t smem_u32(const void* p) {
    uint32_t a;
    asm("{ .reg .u64 t; cvta.to.shared.u64 t, %1; cvt.u32.u64 %0, t; }"
        : "=r"(a) : "l"(p));
    return a;
}
__device__ __forceinline__ void ldsm_x4(uint32_t& r0, uint32_t& r1,
                                        uint32_t& r2, uint32_t& r3, uint32_t addr) {
    asm volatile("ldmatrix.sync.aligned.m8n8.x4.shared.b16 {%0,%1,%2,%3}, [%4];"
        : "=r"(r0), "=r"(r1), "=r"(r2), "=r"(r3) : "r"(addr));
}
__device__ __forceinline__ void mma16816(float* c, uint32_t a0, uint32_t a1,
                                         uint32_t a2, uint32_t a3,
                                         uint32_t b0, uint32_t b1) {
    asm volatile("mma.sync.aligned.m16n8k16.row.col.f32.bf16.bf16.f32 "
        "{%0,%1,%2,%3}, {%4,%5,%6,%7}, {%8,%9}, {%0,%1,%2,%3};"
        : "+f"(c[0]), "+f"(c[1]), "+f"(c[2]), "+f"(c[3])
        : "r"(a0), "r"(a1), "r"(a2), "r"(a3), "r"(b0), "r"(b1));
}
__device__ __forceinline__ uint32_t packbf(float a, float b) {
    return ((uint32_t)__bfloat16_as_ushort(__float2bfloat16_rn(b)) << 16) |
            (uint32_t)__bfloat16_as_ushort(__float2bfloat16_rn(a));
}
#define CP_ASYNC16(dst, src) \
    asm volatile("cp.async.cg.shared.global [%0], [%1], 16;" \
        :: "r"(dst), "l"(src) : "memory")
#define CP_COMMIT() asm volatile("cp.async.commit_group;" ::: "memory")
#define CP_WAIT(n)  asm volatile("cp.async.wait_group %0;" :: "n"(n) : "memory")

// ---------------------------------------------------------------------------
// init: warp per E row — |e|^2 (fp64, shuffle-reduced), bf16 convert, zeroing
// ---------------------------------------------------------------------------
__global__ void __launch_bounds__(256) k_init(const float* __restrict__ E) {
    const int warp = threadIdx.x >> 5;
    const int lane = threadIdx.x & 31;
    const int row  = blockIdx.x * 8 + warp;

    float4 v = ((const float4*)(E + (size_t)row * D_N))[lane];
    double s = 0.0;
    s += (double)v.x * (double)v.x;
    s += (double)v.y * (double)v.y;
    s += (double)v.z * (double)v.z;
    s += (double)v.w * (double)v.w;
    #pragma unroll
    for (int off = 16; off > 0; off >>= 1)
        s += __shfl_xor_sync(0xffffffffu, s, off);

    uint2 o;
    o.x = packbf(v.x, v.y);
    o.y = packbf(v.z, v.w);
    ((uint2*)g_eb)[(size_t)row * 32 + lane] = o;

    if (lane == 0) { g_esq[row] = (float)s; g_counts[row] = 0; }
    if (row == 0 && lane == 0) { g_sum_e = 0.0; g_sum_q = 0.0; g_done = 0; }
}

// ---------------------------------------------------------------------------
// phase1 (fused): bf16 mma.sync GEMM with per-half register-threshold
// candidate selection (R8-identical main loop), rowmax export, in-CTA rescore
// + gather tail, and last-CTA entropy/scalar epilogue.
// ---------------------------------------------------------------------------
__global__ void __launch_bounds__(256, 2) k_phase1(
    const float* __restrict__ X, const float* __restrict__ E,
    float* __restrict__ out, int out_size)
{
    extern __shared__ char smem[];
    int*   scnt = (int*)  (smem + SCNT_OFF);   // [128]
    float* rmax = (float*)(smem + RMAX_OFF);   // [128][2]

    const int tid  = threadIdx.x;
    const int lane = tid & 31;
    const int wid  = tid >> 5;
    const int wm   = wid >> 1;          // 0..3  (rows 32*wm .. +32)
    const int wn   = wid & 1;           // 0..1  (cols 64*wn .. +64)
    const int row0 = blockIdx.x * 128;

    if (tid < 128) scnt[tid] = 0;

    const uint32_t sb = smem_u32(smem);

    // issue E tile 0 via cp.async (group 0)
    #pragma unroll
    for (int i = 0; i < 8; i++) {
        int m = tid + i * 256; int r = m >> 4, c16 = m & 15;
        uint32_t dst = sb + E0_OFF + (uint32_t)(r * ROWB + c16 * 16);
        const char* src = (const char*)g_eb + (size_t)r * 256 + c16 * 16;
        CP_ASYNC16(dst, src);
    }
    CP_COMMIT();

    // X tile: load fp32, convert to bf16, store padded (overlaps with cp.async)
    #pragma unroll
    for (int i = 0; i < 8; i++) {
        int m = tid + i * 256; int r = m >> 4, c16 = m & 15;
        float4 f0 = ((const float4*)X)[(size_t)(row0 + r) * 32 + c16 * 2];
        float4 f1 = ((const float4*)X)[(size_t)(row0 + r) * 32 + c16 * 2 + 1];
        uint4 o;
        o.x = packbf(f0.x, f0.y);
        o.y = packbf(f0.z, f0.w);
        o.z = packbf(f1.x, f1.y);
        o.w = packbf(f1.z, f1.w);
        *(uint4*)(smem + XS_OFF + r * ROWB + c16 * 16) = o;
    }
    __syncthreads();

    const uint32_t pA = sb + XS_OFF + (uint32_t)((wm * 32 + (lane & 15)) * ROWB)
                        + (uint32_t)((lane >> 4) * 8 * 2);
    const int n_lane = ((lane >> 4) << 3) + (lane & 7);
    const uint32_t pB_off = (uint32_t)((wn * 64 + n_lane) * ROWB)
                            + (uint32_t)(((lane >> 3) & 1) * 8 * 2);

    const int qr = lane >> 2;           // quad row id 0..7
    const int qc = lane & 3;

    // per-half running row maxima (registers)
    float thrA[2] = { -CUDART_INF_F, -CUDART_INF_F };
    float thrB[2] = { -CUDART_INF_F, -CUDART_INF_F };

    for (int t = 0; t < NTILES; t++) {
        const int buf = t & 1;

        // stage tile t+1 into the other buffer, then wait for tile t
        if (t + 1 < NTILES) {
            const int nb = (t + 1) & 1;
            const uint32_t ebase = sb + (nb ? E1_OFF : E0_OFF);
            #pragma unroll
            for (int i = 0; i < 8; i++) {
                int m = tid + i * 256; int r = m >> 4, c16 = m & 15;
                uint32_t dst = ebase + (uint32_t)(r * ROWB + c16 * 16);
                const char* src = (const char*)g_eb
                                  + (size_t)((t + 1) * 128 + r) * 256 + c16 * 16;
                CP_ASYNC16(dst, src);
            }
            CP_COMMIT();
            CP_WAIT(1);
        } else {
            CP_WAIT(0);
        }
        __syncthreads();

        const uint32_t pB = sb + (buf ? E1_OFF : E0_OFF) + pB_off;

        float acc[2][8][4];
        #pragma unroll
        for (int mt = 0; mt < 2; mt++)
            #pragma unroll
            for (int nt = 0; nt < 8; nt++)
                #pragma unroll
                for (int j = 0; j < 4; j++) acc[mt][nt][j] = 0.0f;

        #pragma unroll
        for (int s = 0; s < 8; s++) {
            uint32_t a[2][4];
            #pragma unroll
            for (int mt = 0; mt < 2; mt++)
                ldsm_x4(a[mt][0], a[mt][1], a[mt][2], a[mt][3],
                        pA + (uint32_t)(mt * 16 * ROWB) + (uint32_t)(s * 32));
            uint32_t b[4][4];
            #pragma unroll
            for (int p = 0; p < 4; p++)
                ldsm_x4(b[p][0], b[p][1], b[p][2], b[p][3],
                        pB + (uint32_t)(p * 16 * ROWB) + (uint32_t)(s * 32));
            #pragma unroll
            for (int mt = 0; mt < 2; mt++)
                #pragma unroll
                for (int nt = 0; nt < 8; nt++) {
                    uint32_t b0 = (nt & 1) ? b[nt >> 1][2] : b[nt >> 1][0];
                    uint32_t b1 = (nt & 1) ? b[nt >> 1][3] : b[nt >> 1][1];
                    mma16816(acc[mt][nt], a[mt][0], a[mt][1], a[mt][2], a[mt][3],
                             b0, b1);
                }
        }

        // ---- epilogue: warp-local row maxima, guarded emission ----
        #pragma unroll
        for (int mt = 0; mt < 2; mt++) {
            float ma = -CUDART_INF_F, mb = -CUDART_INF_F;
            #pragma unroll
            for (int nt = 0; nt < 8; nt++) {
                ma = fmaxf(ma, fmaxf(acc[mt][nt][0], acc[mt][nt][1]));
                mb = fmaxf(mb, fmaxf(acc[mt][nt][2], acc[mt][nt][3]));
            }
            ma = fmaxf(ma, __shfl_xor_sync(0xffffffffu, ma, 1));
            ma = fmaxf(ma, __shfl_xor_sync(0xffffffffu, ma, 2));
            mb = fmaxf(mb, __shfl_xor_sync(0xffffffffu, mb, 1));
            mb = fmaxf(mb, __shfl_xor_sync(0xffffffffu, mb, 2));
            const bool anyA = (ma >= thrA[mt] - DELTA_C);
            const bool anyB = (mb >= thrB[mt] - DELTA_C);
            thrA[mt] = fmaxf(thrA[mt], ma);
            thrB[mt] = fmaxf(thrB[mt], mb);
            const int rA = wm * 32 + mt * 16 + qr;
            const int rB = rA + 8;
            if (anyA) {
                const float cutA = thrA[mt] - DELTA_C;
                #pragma unroll
                for (int nt = 0; nt < 8; nt++) {
                    int kb = t * 128 + wn * 64 + nt * 8 + 2 * qc;
                    if (acc[mt][nt][0] >= cutA) {
                        int p = atomicAdd(&scnt[rA], 1);
                        if (p < CAP) g_cand[(size_t)(row0 + rA) * CAP + p] =
                            make_int2(__float_as_int(acc[mt][nt][0]), kb);
                    }
                    if (acc[mt][nt][1] >= cutA) {
                        int p = atomicAdd(&scnt[rA], 1);
                        if (p < CAP) g_cand[(size_t)(row0 + rA) * CAP + p] =
                            make_int2(__float_as_int(acc[mt][nt][1]), kb + 1);
                    }
                }
            }
            if (anyB) {
                const float cutB = thrB[mt] - DELTA_C;
                #pragma unroll
                for (int nt = 0; nt < 8; nt++) {
                    int kb = t * 128 + wn * 64 + nt * 8 + 2 * qc;
                    if (acc[mt][nt][2] >= cutB) {
                        int p = atomicAdd(&scnt[rB], 1);
                        if (p < CAP) g_cand[(size_t)(row0 + rB) * CAP + p] =
                            make_int2(__float_as_int(acc[mt][nt][2]), kb);
                    }
                    if (acc[mt][nt][3] >= cutB) {
                        int p = atomicAdd(&scnt[rB], 1);
                        if (p < CAP) g_cand[(size_t)(row0 + rB) * CAP + p] =
                            make_int2(__float_as_int(acc[mt][nt][3]), kb + 1);
                    }
                }
            }
        }
        __syncthreads();
    }

    // export final per-half row maxima (all 4 quad lanes hold the value; qc==0 writes)
    if (qc == 0) {
        #pragma unroll
        for (int mt = 0; mt < 2; mt++) {
            int rA = wm * 32 + mt * 16 + qr;
            rmax[rA * 2 + wn] = thrA[mt];
            rmax[(rA + 8) * 2 + wn] = thrB[mt];
        }
    }

    // ======================= fused rescore + gather tail =====================
    float*  xsf   = (float*) (smem + TXS_OFF);   // [16][132] fp32 x chunk
    int*    slist = (int*)   (smem + TSL_OFF);   // [16][CAP]
    int*    scnt2 = (int*)   (smem + TSC_OFF);   // [16]
    double* swe   = (double*)(smem + TSW_OFF);   // [8]
    double* swq   = swe + 8;                     // [8]
    int*    sflag = (int*)(swq + 8);

    const int grp = lane >> 4;      // 0..1: row within warp
    const int l16 = lane & 15;      // lane within 16-lane group
    const int rowL = wid * 2 + grp; // 0..15 within chunk

    double se_tot = 0.0, sq_tot = 0.0;

    for (int c = 0; c < 8; c++) {
        __syncthreads();
        // load fp32 X for rows [row0 + c*16, +16)
        #pragma unroll
        for (int i = 0; i < 2; i++) {
            int m = tid + i * 256;          // 0..511
            int r = m >> 5, cc = m & 31;
            float4 v = ((const float4*)X)[(size_t)(row0 + c * 16 + r) * 32 + cc];
            *(float4*)&xsf[r * 132 + cc * 4] = v;
        }
        if (tid < 16) scnt2[tid] = 0;
        __syncthreads();

        const int lrow = c * 16 + rowL;     // 0..127
        const int row  = row0 + lrow;
        const float* xr = &xsf[rowL * 132];

        // A = |x|^2 in fp64, reduced within the 16-lane group
        double s = 0.0;
        #pragma unroll
        for (int i = 0; i < 8; i++) { double v = (double)xr[l16 * 8 + i]; s += v * v; }
        #pragma unroll
        for (int off = 1; off < 16; off <<= 1)
            s += __shfl_xor_sync(0xffffffffu, s, off);
        float A = (float)s;

        int n = scnt[lrow];
        float best = CUDART_INF_F;
        int bi = 0x7fffffff;

        if (n <= CAP) {
            const int2* cd = &g_cand[(size_t)row * CAP];
            // global row max from GEMM registers (exported above)
            const float cut = fmaxf(rmax[lrow * 2], rmax[lrow * 2 + 1]) - DELTA_C;
            // compact survivors into smem
            for (int j = l16; j < n; j += 16) {
                int2 cc2 = cd[j];
                if (__int_as_float(cc2.x) >= cut) {
                    int p = atomicAdd(&scnt2[rowL], 1);
                    slist[rowL * CAP + p] = cc2.y;
                }
            }
            __syncwarp();
            const int m = scnt2[rowL];
            for (int si = l16; si < m; si += 16) {
                int k = slist[rowL * CAP + si];
                const float4* e4 = (const float4*)(E + (size_t)k * D_N);
                float acc = 0.0f;
                #pragma unroll 8
                for (int i = 0; i < 32; i++) {
                    float4 xv = *(const float4*)&xr[i * 4];
                    float4 ev = e4[i];
                    acc = __fmaf_rn(xv.x, ev.x, acc);
                    acc = __fmaf_rn(xv.y, ev.y, acc);
                    acc = __fmaf_rn(xv.z, ev.z, acc);
                    acc = __fmaf_rn(xv.w, ev.w, acc);
                }
                float tsum = __fadd_rn(A, g_esq[k]);
                float v = __fmaf_rn(-2.0f, acc, tsum);
                if (v < best || (v == best && k < bi)) { best = v; bi = k; }
            }
        } else {
            // safety fallback: exact full scan (unreachable in practice)
            for (int k = l16; k < K_N; k += 16) {
                const float4* e4 = (const float4*)(E + (size_t)k * D_N);
                float acc = 0.0f;
                #pragma unroll 8
                for (int i = 0; i < 32; i++) {
                    float4 xv = *(const float4*)&xr[i * 4];
                    float4 ev = e4[i];
                    acc = __fmaf_rn(xv.x, ev.x, acc);
                    acc = __fmaf_rn(xv.y, ev.y, acc);
                    acc = __fmaf_rn(xv.z, ev.z, acc);
                    acc = __fmaf_rn(xv.w, ev.w, acc);
                }
                float tsum = __fadd_rn(A, g_esq[k]);
                float v = __fmaf_rn(-2.0f, acc, tsum);
                if (v < best || (v == best && k < bi)) { best = v; bi = k; }
            }
        }
        // butterfly reduce within 16-lane group -> all lanes hold (best, bi)
        #pragma unroll
        for (int off = 1; off < 16; off <<= 1) {
            float ov = __shfl_xor_sync(0xffffffffu, best, off);
            int   oi = __shfl_xor_sync(0xffffffffu, bi, off);
            if (ov < best || (ov == best && oi < bi)) { best = ov; bi = oi; }
        }

        // ---- gather: straight-through output + loss sums + histogram ----
        const float4* e4 = (const float4*)(E + (size_t)bi * D_N);
        float4 q0 = e4[l16 * 2], q1 = e4[l16 * 2 + 1];
        float4 x0 = *(const float4*)&xr[l16 * 8];
        float4 x1 = *(const float4*)&xr[l16 * 8 + 4];
        float4 o0, o1;
#define VQ_STEP(o, q, x) { \
        float de = __fsub_rn(q, x); float qs = __fadd_rn(x, de); \
        float dq = __fsub_rn(qs, x); \
        o = qs; se_tot += (double)de * (double)de; sq_tot += (double)dq * (double)dq; }
        VQ_STEP(o0.x, q0.x, x0.x)  VQ_STEP(o0.y, q0.y, x0.y)
        VQ_STEP(o0.z, q0.z, x0.z)  VQ_STEP(o0.w, q0.w, x0.w)
        VQ_STEP(o1.x, q1.x, x1.x)  VQ_STEP(o1.y, q1.y, x1.y)
        VQ_STEP(o1.z, q1.z, x1.z)  VQ_STEP(o1.w, q1.w, x1.w)
#undef VQ_STEP
        ((float4*)out)[(size_t)row * 32 + l16 * 2]     = o0;
        ((float4*)out)[(size_t)row * 32 + l16 * 2 + 1] = o1;

        if (l16 == 0) {
            atomicAdd(&g_counts[bi], 1);
            if (out_size >= B_N * D_N + B_N)
                out[(size_t)B_N * D_N + row] = (float)bi;
        }
    }

    // block-reduce loss sums (once per CTA)
    #pragma unroll
    for (int off = 16; off > 0; off >>= 1) {
        se_tot += __shfl_down_sync(0xffffffffu, se_tot, off);
        sq_tot += __shfl_down_sync(0xffffffffu, sq_tot, off);
    }
    if (lane == 0) { swe[wid] = se_tot; swq[wid] = sq_tot; }
    __syncthreads();
    if (tid == 0) {
        double te = 0.0, tq = 0.0;
        #pragma unroll
        for (int i = 0; i < 8; i++) { te += swe[i]; tq += swq[i]; }
        atomicAdd(&g_sum_e, te);
        atomicAdd(&g_sum_q, tq);
        __threadfence();
        int d = atomicAdd(&g_done, 1);
        sflag[0] = (d == gridDim.x - 1) ? 1 : 0;
    }
    __syncthreads();

    // ---- last CTA: entropy + scalar outputs ----
    if (sflag[0] && out_size >= B_N * D_N + B_N + 4) {
        double* sh = (double*)(smem + TXS_OFF);   // 256 doubles
        double h = 0.0;
        #pragma unroll
        for (int r = 0; r < K_N / 256; r++) {
            int k = r * 256 + tid;
            int cnt = __ldcg(&g_counts[k]);
            float p = __fmul_rn((float)cnt, 1.0f / 32768.0f);
            float t = __fmul_rn(p, logf(__fadd_rn(p, 1e-10f)));
            h += (double)t;
        }
        sh[tid] = h;
        __syncthreads();
        for (int s = 128; s > 0; s >>= 1) {
            if (tid < s) sh[tid] += sh[tid + s];
            __syncthreads();
        }
        if (tid == 0) {
            float H = (float)sh[0];
            float perp = expf(-H);
            double nrm = (double)B_N * (double)D_N;
            float e = (float)(__ldcg(&g_sum_e) / nrm);
            float q = (float)(__ldcg(&g_sum_q) / nrm);
            float vq = __fadd_rn(q, __fmul_rn(0.25f, e));
            float* s4 = out + (size_t)B_N * D_N + B_N;
            s4[0] = vq; s4[1] = e; s4[2] = q; s4[3] = perp;
        }
    }
}

// ---------------------------------------------------------------------------
extern "C" void kernel_launch(void* const* d_in, const int* in_sizes, int n_in,
                              void* d_out, int out_size)
{
    const float* X = (const float*)d_in[0];
    const float* E = (const float*)d_in[1];
    if (n_in >= 2 && in_sizes[0] == K_N * D_N && in_sizes[1] == B_N * D_N) {
        X = (const float*)d_in[1];
        E = (const float*)d_in[0];
    }
    float* out = (float*)d_out;

    static bool attr_set = false;
    if (!attr_set) {
        cudaFuncSetAttribute(k_phase1,
                             cudaFuncAttributeMaxDynamicSharedMemorySize,
                             SM_TOTAL);
        attr_set = true;
    }

    k_init<<<K_N / 8, 256>>>(E);
    k_phase1<<<B_N / 128, 256, SM_TOTAL>>>(X, E, out, out_size);
}

// round 15
// speedup vs baseline: 1.0473x; 1.0345x over previous
#include <cuda_runtime.h>
#include <cuda_bf16.h>
#include <math_constants.h>
#include <cstdint>

#define B_N 32768
#define D_N 128
#define K_N 4096
#define CAP 128
#define DELTA_C 2.5e-4f
#define NTILES 32

// phase-1 smem layout (bytes). Rows padded to 272B (136 bf16) for conflict-free LDSM.
#define ROWB 272
#define XS_OFF   0
#define E0_OFF   34816
#define E1_OFF   69632
#define SCNT_OFF 104448
#define RMAX_OFF 104960                   // [128][2] float row maxima
#define SM_TOTAL 105984

// tail (rescore) smem layout — reuses [0, SCNT_OFF) after the MMA loop
#define TXS_OFF   0                       // fp32 x ALL rows [128][132] = 67584 B
#define TSL_OFF   67584                   // slist [128][16] int = 8192 B
#define TSC_OFF   75776                   // scnt2 [128] int = 512 B
#define TSW_OFF   76288                   // swe[8], swq[8], flag
#define SLCAP 16

__device__ __nv_bfloat16 g_eb[K_N * D_N];
__device__ int2   g_cand[(size_t)B_N * CAP];   // .x = bf16-GEMM score bits, .y = index
__device__ float  g_esq[K_N];
__device__ int    g_counts[K_N];
__device__ double g_sum_e, g_sum_q;
__device__ int    g_done;

__device__ __forceinline__ uint32_t smem_u32(const void* p) {
    uint32_t a;
    asm("{ .reg .u64 t; cvta.to.shared.u64 t, %1; cvt.u32.u64 %0, t; }"
        : "=r"(a) : "l"(p));
    return a;
}
__device__ __forceinline__ void ldsm_x4(uint32_t& r0, uint32_t& r1,
                                        uint32_t& r2, uint32_t& r3, uint32_t addr) {
    asm volatile("ldmatrix.sync.aligned.m8n8.x4.shared.b16 {%0,%1,%2,%3}, [%4];"
        : "=r"(r0), "=r"(r1), "=r"(r2), "=r"(r3) : "r"(addr));
}
__device__ __forceinline__ void mma16816(float* c, uint32_t a0, uint32_t a1,
                                         uint32_t a2, uint32_t a3,
                                         uint32_t b0, uint32_t b1) {
    asm volatile("mma.sync.aligned.m16n8k16.row.col.f32.bf16.bf16.f32 "
        "{%0,%1,%2,%3}, {%4,%5,%6,%7}, {%8,%9}, {%0,%1,%2,%3};"
        : "+f"(c[0]), "+f"(c[1]), "+f"(c[2]), "+f"(c[3])
        : "r"(a0), "r"(a1), "r"(a2), "r"(a3), "r"(b0), "r"(b1));
}
__device__ __forceinline__ uint32_t packbf(float a, float b) {
    return ((uint32_t)__bfloat16_as_ushort(__float2bfloat16_rn(b)) << 16) |
            (uint32_t)__bfloat16_as_ushort(__float2bfloat16_rn(a));
}
#define CP_ASYNC16(dst, src) \
    asm volatile("cp.async.cg.shared.global [%0], [%1], 16;" \
        :: "r"(dst), "l"(src) : "memory")
#define CP_COMMIT() asm volatile("cp.async.commit_group;" ::: "memory")
#define CP_WAIT(n)  asm volatile("cp.async.wait_group %0;" :: "n"(n) : "memory")

// ---------------------------------------------------------------------------
// init: warp per E row — |e|^2 (fp64, shuffle-reduced), bf16 convert, zeroing
// ---------------------------------------------------------------------------
__global__ void __launch_bounds__(256) k_init(const float* __restrict__ E) {
    const int warp = threadIdx.x >> 5;
    const int lane = threadIdx.x & 31;
    const int row  = blockIdx.x * 8 + warp;

    float4 v = ((const float4*)(E + (size_t)row * D_N))[lane];
    double s = 0.0;
    s += (double)v.x * (double)v.x;
    s += (double)v.y * (double)v.y;
    s += (double)v.z * (double)v.z;
    s += (double)v.w * (double)v.w;
    #pragma unroll
    for (int off = 16; off > 0; off >>= 1)
        s += __shfl_xor_sync(0xffffffffu, s, off);

    uint2 o;
    o.x = packbf(v.x, v.y);
    o.y = packbf(v.z, v.w);
    ((uint2*)g_eb)[(size_t)row * 32 + lane] = o;

    if (lane == 0) { g_esq[row] = (float)s; g_counts[row] = 0; }
    if (row == 0 && lane == 0) { g_sum_e = 0.0; g_sum_q = 0.0; g_done = 0; }
}

// ---------------------------------------------------------------------------
// phase1 (fused): bf16 mma.sync GEMM with per-half register-threshold
// candidate selection (R8-identical main loop), rowmax export, barrier-free
// in-CTA rescore + gather tail, and last-CTA entropy/scalar epilogue.
// ---------------------------------------------------------------------------
__global__ void __launch_bounds__(256, 2) k_phase1(
    const float* __restrict__ X, const float* __restrict__ E,
    float* __restrict__ out, int out_size)
{
    extern __shared__ char smem[];
    int*   scnt = (int*)  (smem + SCNT_OFF);   // [128]
    float* rmax = (float*)(smem + RMAX_OFF);   // [128][2]

    const int tid  = threadIdx.x;
    const int lane = tid & 31;
    const int wid  = tid >> 5;
    const int wm   = wid >> 1;          // 0..3  (rows 32*wm .. +32)
    const int wn   = wid & 1;           // 0..1  (cols 64*wn .. +64)
    const int row0 = blockIdx.x * 128;

    if (tid < 128) scnt[tid] = 0;

    const uint32_t sb = smem_u32(smem);

    // issue E tile 0 via cp.async (group 0)
    #pragma unroll
    for (int i = 0; i < 8; i++) {
        int m = tid + i * 256; int r = m >> 4, c16 = m & 15;
        uint32_t dst = sb + E0_OFF + (uint32_t)(r * ROWB + c16 * 16);
        const char* src = (const char*)g_eb + (size_t)r * 256 + c16 * 16;
        CP_ASYNC16(dst, src);
    }
    CP_COMMIT();

    // X tile: load fp32, convert to bf16, store padded (overlaps with cp.async)
    #pragma unroll
    for (int i = 0; i < 8; i++) {
        int m = tid + i * 256; int r = m >> 4, c16 = m & 15;
        float4 f0 = ((const float4*)X)[(size_t)(row0 + r) * 32 + c16 * 2];
        float4 f1 = ((const float4*)X)[(size_t)(row0 + r) * 32 + c16 * 2 + 1];
        uint4 o;
        o.x = packbf(f0.x, f0.y);
        o.y = packbf(f0.z, f0.w);
        o.z = packbf(f1.x, f1.y);
        o.w = packbf(f1.z, f1.w);
        *(uint4*)(smem + XS_OFF + r * ROWB + c16 * 16) = o;
    }
    __syncthreads();

    const uint32_t pA = sb + XS_OFF + (uint32_t)((wm * 32 + (lane & 15)) * ROWB)
                        + (uint32_t)((lane >> 4) * 8 * 2);
    const int n_lane = ((lane >> 4) << 3) + (lane & 7);
    const uint32_t pB_off = (uint32_t)((wn * 64 + n_lane) * ROWB)
                            + (uint32_t)(((lane >> 3) & 1) * 8 * 2);

    const int qr = lane >> 2;           // quad row id 0..7
    const int qc = lane & 3;

    // per-half running row maxima (registers)
    float thrA[2] = { -CUDART_INF_F, -CUDART_INF_F };
    float thrB[2] = { -CUDART_INF_F, -CUDART_INF_F };

    for (int t = 0; t < NTILES; t++) {
        const int buf = t & 1;

        // stage tile t+1 into the other buffer, then wait for tile t
        if (t + 1 < NTILES) {
            const int nb = (t + 1) & 1;
            const uint32_t ebase = sb + (nb ? E1_OFF : E0_OFF);
            #pragma unroll
            for (int i = 0; i < 8; i++) {
                int m = tid + i * 256; int r = m >> 4, c16 = m & 15;
                uint32_t dst = ebase + (uint32_t)(r * ROWB + c16 * 16);
                const char* src = (const char*)g_eb
                                  + (size_t)((t + 1) * 128 + r) * 256 + c16 * 16;
                CP_ASYNC16(dst, src);
            }
            CP_COMMIT();
            CP_WAIT(1);
        } else {
            CP_WAIT(0);
        }
        __syncthreads();

        const uint32_t pB = sb + (buf ? E1_OFF : E0_OFF) + pB_off;

        float acc[2][8][4];
        #pragma unroll
        for (int mt = 0; mt < 2; mt++)
            #pragma unroll
            for (int nt = 0; nt < 8; nt++)
                #pragma unroll
                for (int j = 0; j < 4; j++) acc[mt][nt][j] = 0.0f;

        #pragma unroll
        for (int s = 0; s < 8; s++) {
            uint32_t a[2][4];
            #pragma unroll
            for (int mt = 0; mt < 2; mt++)
                ldsm_x4(a[mt][0], a[mt][1], a[mt][2], a[mt][3],
                        pA + (uint32_t)(mt * 16 * ROWB) + (uint32_t)(s * 32));
            uint32_t b[4][4];
            #pragma unroll
            for (int p = 0; p < 4; p++)
                ldsm_x4(b[p][0], b[p][1], b[p][2], b[p][3],
                        pB + (uint32_t)(p * 16 * ROWB) + (uint32_t)(s * 32));
            #pragma unroll
            for (int mt = 0; mt < 2; mt++)
                #pragma unroll
                for (int nt = 0; nt < 8; nt++) {
                    uint32_t b0 = (nt & 1) ? b[nt >> 1][2] : b[nt >> 1][0];
                    uint32_t b1 = (nt & 1) ? b[nt >> 1][3] : b[nt >> 1][1];
                    mma16816(acc[mt][nt], a[mt][0], a[mt][1], a[mt][2], a[mt][3],
                             b0, b1);
                }
        }

        // ---- epilogue: warp-local row maxima, guarded emission ----
        #pragma unroll
        for (int mt = 0; mt < 2; mt++) {
            float ma = -CUDART_INF_F, mb = -CUDART_INF_F;
            #pragma unroll
            for (int nt = 0; nt < 8; nt++) {
                ma = fmaxf(ma, fmaxf(acc[mt][nt][0], acc[mt][nt][1]));
                mb = fmaxf(mb, fmaxf(acc[mt][nt][2], acc[mt][nt][3]));
            }
            ma = fmaxf(ma, __shfl_xor_sync(0xffffffffu, ma, 1));
            ma = fmaxf(ma, __shfl_xor_sync(0xffffffffu, ma, 2));
            mb = fmaxf(mb, __shfl_xor_sync(0xffffffffu, mb, 1));
            mb = fmaxf(mb, __shfl_xor_sync(0xffffffffu, mb, 2));
            const bool anyA = (ma >= thrA[mt] - DELTA_C);
            const bool anyB = (mb >= thrB[mt] - DELTA_C);
            thrA[mt] = fmaxf(thrA[mt], ma);
            thrB[mt] = fmaxf(thrB[mt], mb);
            const int rA = wm * 32 + mt * 16 + qr;
            const int rB = rA + 8;
            if (anyA) {
                const float cutA = thrA[mt] - DELTA_C;
                #pragma unroll
                for (int nt = 0; nt < 8; nt++) {
                    int kb = t * 128 + wn * 64 + nt * 8 + 2 * qc;
                    if (acc[mt][nt][0] >= cutA) {
                        int p = atomicAdd(&scnt[rA], 1);
                        if (p < CAP) g_cand[(size_t)(row0 + rA) * CAP + p] =
                            make_int2(__float_as_int(acc[mt][nt][0]), kb);
                    }
                    if (acc[mt][nt][1] >= cutA) {
                        int p = atomicAdd(&scnt[rA], 1);
                        if (p < CAP) g_cand[(size_t)(row0 + rA) * CAP + p] =
                            make_int2(__float_as_int(acc[mt][nt][1]), kb + 1);
                    }
                }
            }
            if (anyB) {
                const float cutB = thrB[mt] - DELTA_C;
                #pragma unroll
                for (int nt = 0; nt < 8; nt++) {
                    int kb = t * 128 + wn * 64 + nt * 8 + 2 * qc;
                    if (acc[mt][nt][2] >= cutB) {
                        int p = atomicAdd(&scnt[rB], 1);
                        if (p < CAP) g_cand[(size_t)(row0 + rB) * CAP + p] =
                            make_int2(__float_as_int(acc[mt][nt][2]), kb);
                    }
                    if (acc[mt][nt][3] >= cutB) {
                        int p = atomicAdd(&scnt[rB], 1);
                        if (p < CAP) g_cand[(size_t)(row0 + rB) * CAP + p] =
                            make_int2(__float_as_int(acc[mt][nt][3]), kb + 1);
                    }
                }
            }
        }
        __syncthreads();
    }

    // export final per-half row maxima (all 4 quad lanes hold the value; qc==0 writes)
    if (qc == 0) {
        #pragma unroll
        for (int mt = 0; mt < 2; mt++) {
            int rA = wm * 32 + mt * 16 + qr;
            rmax[rA * 2 + wn] = thrA[mt];
            rmax[(rA + 8) * 2 + wn] = thrB[mt];
        }
    }
    __syncthreads();

    // ================= barrier-free fused rescore + gather tail ===============
    float*  xsf   = (float*) (smem + TXS_OFF);   // [128][132] fp32 x
    int*    slist = (int*)   (smem + TSL_OFF);   // [128][SLCAP]
    int*    scnt2 = (int*)   (smem + TSC_OFF);   // [128]
    double* swe   = (double*)(smem + TSW_OFF);   // [8]
    double* swq   = swe + 8;                     // [8]
    int*    sflag = (int*)(swq + 8);

    // load ALL fp32 X rows for this CTA (one coalesced pass)
    #pragma unroll
    for (int i = 0; i < 16; i++) {
        int m = tid + i * 256;          // 0..4095
        int r = m >> 5, cc = m & 31;
        float4 v = ((const float4*)X)[(size_t)(row0 + r) * 32 + cc];
        *(float4*)&xsf[r * 132 + cc * 4] = v;
    }
    if (tid < 128) scnt2[tid] = 0;
    __syncthreads();

    const int grp = lane >> 4;      // 0..1: row within pair
    const int l16 = lane & 15;      // lane within 16-lane group

    double se_tot = 0.0, sq_tot = 0.0;

    for (int rr = 0; rr < 8; rr++) {
        const int lrow = wid * 16 + rr * 2 + grp;   // 0..127, warp-private range
        const int row  = row0 + lrow;
        const float* xr = &xsf[lrow * 132];

        // A = |x|^2 in fp64, reduced within the 16-lane group
        double s = 0.0;
        #pragma unroll
        for (int i = 0; i < 8; i++) { double v = (double)xr[l16 * 8 + i]; s += v * v; }
        #pragma unroll
        for (int off = 1; off < 16; off <<= 1)
            s += __shfl_xor_sync(0xffffffffu, s, off);
        float A = (float)s;

        int n = scnt[lrow];
        float best = CUDART_INF_F;
        int bi = 0x7fffffff;

        if (n <= CAP) {
            const int2* cd = &g_cand[(size_t)row * CAP];
            const float cut = fmaxf(rmax[lrow * 2], rmax[lrow * 2 + 1]) - DELTA_C;
            // compact survivors into smem (warp-private rows -> __syncwarp enough)
            for (int j = l16; j < n; j += 16) {
                int2 cc2 = cd[j];
                if (__int_as_float(cc2.x) >= cut) {
                    int p = atomicAdd(&scnt2[lrow], 1);
                    if (p < SLCAP) slist[lrow * SLCAP + p] = cc2.y;
                }
            }
            __syncwarp();
            const int m = scnt2[lrow];
            if (m <= SLCAP) {
                if (l16 < m) {
                    int k = slist[lrow * SLCAP + l16];
                    const float4* e4 = (const float4*)(E + (size_t)k * D_N);
                    float acc = 0.0f;
                    #pragma unroll 8
                    for (int i = 0; i < 32; i++) {
                        float4 xv = *(const float4*)&xr[i * 4];
                        float4 ev = e4[i];
                        acc = __fmaf_rn(xv.x, ev.x, acc);
                        acc = __fmaf_rn(xv.y, ev.y, acc);
                        acc = __fmaf_rn(xv.z, ev.z, acc);
                        acc = __fmaf_rn(xv.w, ev.w, acc);
                    }
                    float tsum = __fadd_rn(A, g_esq[k]);
                    float v = __fmaf_rn(-2.0f, acc, tsum);
                    if (v < best || (v == best && k < bi)) { best = v; bi = k; }
                }
            } else {
                // rare: survivor overflow — direct filtered scan over candidates
                for (int j = l16; j < n; j += 16) {
                    int2 cc2 = cd[j];
                    if (__int_as_float(cc2.x) < cut) continue;
                    int k = cc2.y;
                    const float4* e4 = (const float4*)(E + (size_t)k * D_N);
                    float acc = 0.0f;
                    #pragma unroll 8
                    for (int i = 0; i < 32; i++) {
                        float4 xv = *(const float4*)&xr[i * 4];
                        float4 ev = e4[i];
                        acc = __fmaf_rn(xv.x, ev.x, acc);
                        acc = __fmaf_rn(xv.y, ev.y, acc);
                        acc = __fmaf_rn(xv.z, ev.z, acc);
                        acc = __fmaf_rn(xv.w, ev.w, acc);
                    }
                    float tsum = __fadd_rn(A, g_esq[k]);
                    float v = __fmaf_rn(-2.0f, acc, tsum);
                    if (v < best || (v == best && k < bi)) { best = v; bi = k; }
                }
            }
        } else {
            // safety fallback: exact full scan (unreachable in practice)
            for (int k = l16; k < K_N; k += 16) {
                const float4* e4 = (const float4*)(E + (size_t)k * D_N);
                float acc = 0.0f;
                #pragma unroll 8
                for (int i = 0; i < 32; i++) {
                    float4 xv = *(const float4*)&xr[i * 4];
                    float4 ev = e4[i];
                    acc = __fmaf_rn(xv.x, ev.x, acc);
                    acc = __fmaf_rn(xv.y, ev.y, acc);
                    acc = __fmaf_rn(xv.z, ev.z, acc);
                    acc = __fmaf_rn(xv.w, ev.w, acc);
                }
                float tsum = __fadd_rn(A, g_esq[k]);
                float v = __fmaf_rn(-2.0f, acc, tsum);
                if (v < best || (v == best && k < bi)) { best = v; bi = k; }
            }
        }
        // butterfly reduce within 16-lane group -> all lanes hold (best, bi)
        #pragma unroll
        for (int off = 1; off < 16; off <<= 1) {
            float ov = __shfl_xor_sync(0xffffffffu, best, off);
            int   oi = __shfl_xor_sync(0xffffffffu, bi, off);
            if (ov < best || (ov == best && oi < bi)) { best = ov; bi = oi; }
        }

        // ---- gather: straight-through output + loss sums + histogram ----
        const float4* e4 = (const float4*)(E + (size_t)bi * D_N);
        float4 q0 = e4[l16 * 2], q1 = e4[l16 * 2 + 1];
        float4 x0 = *(const float4*)&xr[l16 * 8];
        float4 x1 = *(const float4*)&xr[l16 * 8 + 4];
        float4 o0, o1;
#define VQ_STEP(o, q, x) { \
        float de = __fsub_rn(q, x); float qs = __fadd_rn(x, de); \
        float dq = __fsub_rn(qs, x); \
        o = qs; se_tot += (double)de * (double)de; sq_tot += (double)dq * (double)dq; }
        VQ_STEP(o0.x, q0.x, x0.x)  VQ_STEP(o0.y, q0.y, x0.y)
        VQ_STEP(o0.z, q0.z, x0.z)  VQ_STEP(o0.w, q0.w, x0.w)
        VQ_STEP(o1.x, q1.x, x1.x)  VQ_STEP(o1.y, q1.y, x1.y)
        VQ_STEP(o1.z, q1.z, x1.z)  VQ_STEP(o1.w, q1.w, x1.w)
#undef VQ_STEP
        ((float4*)out)[(size_t)row * 32 + l16 * 2]     = o0;
        ((float4*)out)[(size_t)row * 32 + l16 * 2 + 1] = o1;

        if (l16 == 0) {
            atomicAdd(&g_counts[bi], 1);
            if (out_size >= B_N * D_N + B_N)
                out[(size_t)B_N * D_N + row] = (float)bi;
        }
    }

    // block-reduce loss sums (once per CTA)
    #pragma unroll
    for (int off = 16; off > 0; off >>= 1) {
        se_tot += __shfl_down_sync(0xffffffffu, se_tot, off);
        sq_tot += __shfl_down_sync(0xffffffffu, sq_tot, off);
    }
    if (lane == 0) { swe[wid] = se_tot; swq[wid] = sq_tot; }
    __syncthreads();
    if (tid == 0) {
        double te = 0.0, tq = 0.0;
        #pragma unroll
        for (int i = 0; i < 8; i++) { te += swe[i]; tq += swq[i]; }
        atomicAdd(&g_sum_e, te);
        atomicAdd(&g_sum_q, tq);
        __threadfence();
        int d = atomicAdd(&g_done, 1);
        sflag[0] = (d == gridDim.x - 1) ? 1 : 0;
    }
    __syncthreads();

    // ---- last CTA: entropy + scalar outputs ----
    if (sflag[0] && out_size >= B_N * D_N + B_N + 4) {
        double* sh = (double*)(smem + TXS_OFF);   // 256 doubles
        double h = 0.0;
        #pragma unroll
        for (int r = 0; r < K_N / 256; r++) {
            int k = r * 256 + tid;
            int cnt = __ldcg(&g_counts[k]);
            float p = __fmul_rn((float)cnt, 1.0f / 32768.0f);
            float t = __fmul_rn(p, logf(__fadd_rn(p, 1e-10f)));
            h += (double)t;
        }
        sh[tid] = h;
        __syncthreads();
        for (int s = 128; s > 0; s >>= 1) {
            if (tid < s) sh[tid] += sh[tid + s];
            __syncthreads();
        }
        if (tid == 0) {
            float H = (float)sh[0];
            float perp = expf(-H);
            double nrm = (double)B_N * (double)D_N;
            float e = (float)(__ldcg(&g_sum_e) / nrm);
            float q = (float)(__ldcg(&g_sum_q) / nrm);
            float vq = __fadd_rn(q, __fmul_rn(0.25f, e));
            float* s4 = out + (size_t)B_N * D_N + B_N;
            s4[0] = vq; s4[1] = e; s4[2] = q; s4[3] = perp;
        }
    }
}

// ---------------------------------------------------------------------------
extern "C" void kernel_launch(void* const* d_in, const int* in_sizes, int n_in,
                              void* d_out, int out_size)
{
    const float* X = (const float*)d_in[0];
    const float* E = (const float*)d_in[1];
    if (n_in >= 2 && in_sizes[0] == K_N * D_N && in_sizes[1] == B_N * D_N) {
        X = (const float*)d_in[1];
        E = (const float*)d_in[0];
    }
    float* out = (float*)d_out;

    static bool attr_set = false;
    if (!attr_set) {
        cudaFuncSetAttribute(k_phase1,
                             cudaFuncAttributeMaxDynamicSharedMemorySize,
                             SM_TOTAL);
        attr_set = true;
    }

    k_init<<<K_N / 8, 256>>>(E);
    k_phase1<<<B_N / 128, 256, SM_TOTAL>>>(X, E, out, out_size);
}